// round 1
// baseline (speedup 1.0000x reference)
#include <cuda_runtime.h>

#define N_USERS 100000
#define N_NODES 150000
#define E_MAX   4800000
#define SCAN_BLK 1024
#define N_SCAN_BLKS 147   // ceil(150000/1024)

// ---------------- static scratch (no allocation allowed) ----------------
__device__ int  d_counts[N_NODES];
__device__ int  d_rowptr[N_NODES];
__device__ int  d_cursor[N_NODES];
__device__ int  d_bsums[256];
__device__ int  d_boff[256];
__device__ int2 d_perm[E_MAX];     // {col, val_bits} interleaved

// ---------------- CSR build ----------------
__global__ void k_zero(int n) {
    int i = blockIdx.x * blockDim.x + threadIdx.x;
    if (i < n) d_counts[i] = 0;
}

__global__ void k_hist(const int* __restrict__ rows, int e) {
    int i = blockIdx.x * blockDim.x + threadIdx.x;
    if (i < e) atomicAdd(&d_counts[rows[i]], 1);
}

__global__ void k_scanA(int n) {
    __shared__ int sh[SCAN_BLK];
    int t = threadIdx.x;
    int idx = blockIdx.x * SCAN_BLK + t;
    int v = (idx < n) ? d_counts[idx] : 0;
    sh[t] = v;
    __syncthreads();
    for (int off = 1; off < SCAN_BLK; off <<= 1) {
        int x = (t >= off) ? sh[t - off] : 0;
        __syncthreads();
        sh[t] += x;
        __syncthreads();
    }
    if (idx < n) d_rowptr[idx] = sh[t] - v;     // exclusive within block
    if (t == SCAN_BLK - 1) d_bsums[blockIdx.x] = sh[t];
}

__global__ void k_scanB(int nb) {
    __shared__ int sh[256];
    int t = threadIdx.x;
    int v = (t < nb) ? d_bsums[t] : 0;
    sh[t] = v;
    __syncthreads();
    for (int off = 1; off < 256; off <<= 1) {
        int x = (t >= off) ? sh[t - off] : 0;
        __syncthreads();
        sh[t] += x;
        __syncthreads();
    }
    d_boff[t] = sh[t] - v;                       // exclusive block offsets
}

__global__ void k_scanC(int n) {
    int t = threadIdx.x;
    int idx = blockIdx.x * SCAN_BLK + t;
    if (idx < n) {
        int val = d_rowptr[idx] + d_boff[blockIdx.x];
        d_rowptr[idx] = val;
        d_cursor[idx] = val;
    }
}

__global__ void k_scatter(const int* __restrict__ rows,
                          const int* __restrict__ cols,
                          const float* __restrict__ vals, int e) {
    int i = blockIdx.x * blockDim.x + threadIdx.x;
    if (i < e) {
        int r = rows[i];
        int p = atomicAdd(&d_cursor[r], 1);
        d_perm[p] = make_int2(cols[i], __float_as_int(vals[i]));
    }
}

// ---------------- write layer-0 embeddings into out[:, 0:64] ----------------
__global__ void k_init(const float4* __restrict__ ue,
                       const float4* __restrict__ ie,
                       float4* __restrict__ out) {
    int i = blockIdx.x * blockDim.x + threadIdx.x;   // over N_NODES*16
    if (i < N_NODES * 16) {
        int node = i >> 4, d4 = i & 15;
        float4 v = (node < N_USERS) ? ue[node * 16 + d4]
                                    : ie[(node - N_USERS) * 16 + d4];
        out[node * 64 + d4] = v;   // out row = 256 floats = 64 float4
    }
}

// ---------------- packed fp32x2 helpers (Blackwell) ----------------
__device__ __forceinline__ unsigned long long pack2(float a, float b) {
    unsigned long long r;
    asm("mov.b64 %0,{%1,%2};" : "=l"(r) : "f"(a), "f"(b));
    return r;
}
__device__ __forceinline__ void unpack2(unsigned long long v, float& a, float& b) {
    asm("mov.b64 {%0,%1},%2;" : "=f"(a), "=f"(b) : "l"(v));
}
__device__ __forceinline__ void ffma2(unsigned long long& acc, float s, float2 w) {
    asm("{\n\t"
        ".reg .b64 sa, wb;\n\t"
        "mov.b64 sa,{%1,%1};\n\t"
        "mov.b64 wb,{%2,%3};\n\t"
        "fma.rn.f32x2 %0, sa, wb, %0;\n\t"
        "}"
        : "+l"(acc) : "f"(s), "f"(w.x), "f"(w.y));
}

// ---------------- fused layer: SpMM + dense + leaky + L2-norm ----------------
__global__ __launch_bounds__(256) void k_layer(
    const float* __restrict__ W1, const float* __restrict__ b1,
    const float* __restrict__ W2, const float* __restrict__ b2,
    float* out, int k, int rows_per_block)
{
    __shared__ float Wsh[128 * 64];   // [i][j]: i<64 -> W1[k][j][i], i>=64 -> W2[k][j][i-64]
    __shared__ float bsh[64];
    __shared__ float ssh[8][128];     // per-warp staged [msg | interact]

    int t = threadIdx.x, lane = t & 31, wid = t >> 5;

    const float* W1k = W1 + k * 4096;
    const float* W2k = W2 + k * 4096;
    for (int idx = t; idx < 128 * 64; idx += 256) {
        int i = idx >> 6, j = idx & 63;
        Wsh[idx] = (i < 64) ? W1k[j * 64 + i] : W2k[j * 64 + (i - 64)];
    }
    if (t < 64) bsh[t] = b1[k * 64 + t] + b2[k * 64 + t];
    __syncthreads();

    const int koff = k * 64;
    int r0 = blockIdx.x * rows_per_block;
    int r1 = min(r0 + rows_per_block, N_NODES);

    for (int r = r0 + wid; r < r1; r += 8) {
        // ---- SpMM: warp gathers this row's message (2 floats per lane) ----
        int start = d_rowptr[r];
        int len   = d_counts[r];
        float a0 = 0.f, a1 = 0.f;
        #pragma unroll 4
        for (int e = start; e < start + len; ++e) {
            int2 cv = d_perm[e];                         // uniform across warp
            float v = __int_as_float(cv.y);
            float2 xv = *(const float2*)(out + (size_t)cv.x * 256 + koff + 2 * lane);
            a0 += v * xv.x;
            a1 += v * xv.y;
        }
        float2 xr = *(const float2*)(out + (size_t)r * 256 + koff + 2 * lane);

        // ---- stage s = [msg | msg*x] into shared ----
        __syncwarp();
        float* s = ssh[wid];
        s[2 * lane]          = a0;
        s[2 * lane + 1]      = a1;
        s[64 + 2 * lane]     = a0 * xr.x;
        s[64 + 2 * lane + 1] = a1 * xr.y;
        __syncwarp();

        // ---- dense: lane computes outputs j = 2*lane, 2*lane+1 ----
        unsigned long long acc = pack2(bsh[2 * lane], bsh[2 * lane + 1]);
        const float2* Wp = (const float2*)Wsh + lane;   // row i at Wp[i*32]
        #pragma unroll
        for (int i = 0; i < 128; i += 4) {
            float4 s4 = *(const float4*)&s[i];          // broadcast LDS.128
            ffma2(acc, s4.x, Wp[(i + 0) * 32]);
            ffma2(acc, s4.y, Wp[(i + 1) * 32]);
            ffma2(acc, s4.z, Wp[(i + 2) * 32]);
            ffma2(acc, s4.w, Wp[(i + 3) * 32]);
        }
        float h0, h1;
        unpack2(acc, h0, h1);
        h0 = h0 > 0.f ? h0 : 0.2f * h0;                 // leaky_relu(0.2)
        h1 = h1 > 0.f ? h1 : 0.2f * h1;

        float sq = h0 * h0 + h1 * h1;
        #pragma unroll
        for (int m = 16; m; m >>= 1) sq += __shfl_xor_sync(0xffffffffu, sq, m);
        float nrm = sqrtf(sq);
        float inv = 1.0f / fmaxf(nrm, 1e-12f);

        *(float2*)(out + (size_t)r * 256 + koff + 64 + 2 * lane) =
            make_float2(h0 * inv, h1 * inv);
    }
}

// ---------------- launch ----------------
extern "C" void kernel_launch(void* const* d_in, const int* in_sizes, int n_in,
                              void* d_out, int out_size) {
    const float* ue   = (const float*)d_in[0];
    const float* ie   = (const float*)d_in[1];
    const float* W1   = (const float*)d_in[2];
    const float* b1   = (const float*)d_in[3];
    const float* W2   = (const float*)d_in[4];
    const float* b2   = (const float*)d_in[5];
    const float* vals = (const float*)d_in[6];
    const int*   rows = (const int*)d_in[7];
    const int*   cols = (const int*)d_in[8];
    float* out = (float*)d_out;
    int e = in_sizes[6];
    int L = in_sizes[2] / (64 * 64);

    // CSR build
    k_zero<<<(N_NODES + 255) / 256, 256>>>(N_NODES);
    k_hist<<<(e + 255) / 256, 256>>>(rows, e);
    k_scanA<<<N_SCAN_BLKS, SCAN_BLK>>>(N_NODES);
    k_scanB<<<1, 256>>>(N_SCAN_BLKS);
    k_scanC<<<N_SCAN_BLKS, SCAN_BLK>>>(N_NODES);
    k_scatter<<<(e + 255) / 256, 256>>>(rows, cols, vals, e);

    // layer 0 embeddings
    k_init<<<(N_NODES * 16 + 255) / 256, 256>>>(
        (const float4*)ue, (const float4*)ie, (float4*)out);

    // fused layers
    const int DG = 1184;                                   // 8 * 148 SMs
    const int rpb = (N_NODES + DG - 1) / DG;               // 127
    for (int k = 0; k < L; ++k)
        k_layer<<<DG, 256>>>(W1, b1, W2, b2, out, k, rpb);
}

// round 2
// speedup vs baseline: 1.0001x; 1.0001x over previous
#include <cuda_runtime.h>

#define N_USERS 100000
#define N_NODES 150000
#define E_MAX   4800000
#define SCAN_BLK 1024
#define N_SCAN_BLKS 147   // ceil(150000/1024)

// ---------------- static scratch (no allocation allowed) ----------------
__device__ int  d_counts[N_NODES];
__device__ int  d_rowptr[N_NODES];
__device__ int  d_cursor[N_NODES];
__device__ int  d_bsums[256];
__device__ int  d_boff[256];
__device__ int2 d_perm[E_MAX];     // {col, val_bits} interleaved

// ---------------- CSR build ----------------
__global__ void k_zero(int n) {
    int i = blockIdx.x * blockDim.x + threadIdx.x;
    if (i < n) d_counts[i] = 0;
}

__global__ void k_hist(const int* __restrict__ rows, int e) {
    int i = blockIdx.x * blockDim.x + threadIdx.x;
    if (i < e) atomicAdd(&d_counts[rows[i]], 1);
}

__global__ void k_scanA(int n) {
    __shared__ int sh[SCAN_BLK];
    int t = threadIdx.x;
    int idx = blockIdx.x * SCAN_BLK + t;
    int v = (idx < n) ? d_counts[idx] : 0;
    sh[t] = v;
    __syncthreads();
    for (int off = 1; off < SCAN_BLK; off <<= 1) {
        int x = (t >= off) ? sh[t - off] : 0;
        __syncthreads();
        sh[t] += x;
        __syncthreads();
    }
    if (idx < n) d_rowptr[idx] = sh[t] - v;     // exclusive within block
    if (t == SCAN_BLK - 1) d_bsums[blockIdx.x] = sh[t];
}

__global__ void k_scanB(int nb) {
    __shared__ int sh[256];
    int t = threadIdx.x;
    int v = (t < nb) ? d_bsums[t] : 0;
    sh[t] = v;
    __syncthreads();
    for (int off = 1; off < 256; off <<= 1) {
        int x = (t >= off) ? sh[t - off] : 0;
        __syncthreads();
        sh[t] += x;
        __syncthreads();
    }
    d_boff[t] = sh[t] - v;                       // exclusive block offsets
}

__global__ void k_scanC(int n) {
    int t = threadIdx.x;
    int idx = blockIdx.x * SCAN_BLK + t;
    if (idx < n) {
        int val = d_rowptr[idx] + d_boff[blockIdx.x];
        d_rowptr[idx] = val;
        d_cursor[idx] = val;
    }
}

__global__ void k_scatter(const int* __restrict__ rows,
                          const int* __restrict__ cols,
                          const float* __restrict__ vals, int e) {
    int i = blockIdx.x * blockDim.x + threadIdx.x;
    if (i < e) {
        int r = rows[i];
        int p = atomicAdd(&d_cursor[r], 1);
        d_perm[p] = make_int2(cols[i], __float_as_int(vals[i]));
    }
}

// ---------------- write layer-0 embeddings into out[:, 0:64] ----------------
__global__ void k_init(const float4* __restrict__ ue,
                       const float4* __restrict__ ie,
                       float4* __restrict__ out) {
    int i = blockIdx.x * blockDim.x + threadIdx.x;   // over N_NODES*16
    if (i < N_NODES * 16) {
        int node = i >> 4, d4 = i & 15;
        float4 v = (node < N_USERS) ? ue[node * 16 + d4]
                                    : ie[(node - N_USERS) * 16 + d4];
        out[node * 64 + d4] = v;   // out row = 256 floats = 64 float4
    }
}

// ---------------- packed fp32x2 helpers (Blackwell) ----------------
__device__ __forceinline__ unsigned long long pack2(float a, float b) {
    unsigned long long r;
    asm("mov.b64 %0,{%1,%2};" : "=l"(r) : "f"(a), "f"(b));
    return r;
}
__device__ __forceinline__ void unpack2(unsigned long long v, float& a, float& b) {
    asm("mov.b64 {%0,%1},%2;" : "=f"(a), "=f"(b) : "l"(v));
}
__device__ __forceinline__ void ffma2(unsigned long long& acc, float s, float2 w) {
    asm("{\n\t"
        ".reg .b64 sa, wb;\n\t"
        "mov.b64 sa,{%1,%1};\n\t"
        "mov.b64 wb,{%2,%3};\n\t"
        "fma.rn.f32x2 %0, sa, wb, %0;\n\t"
        "}"
        : "+l"(acc) : "f"(s), "f"(w.x), "f"(w.y));
}

// ---------------- fused layer: SpMM + dense + leaky + L2-norm ----------------
__global__ __launch_bounds__(256) void k_layer(
    const float* __restrict__ W1, const float* __restrict__ b1,
    const float* __restrict__ W2, const float* __restrict__ b2,
    float* out, int k, int rows_per_block)
{
    __shared__ float Wsh[128 * 64];   // [i][j]: i<64 -> W1[k][j][i], i>=64 -> W2[k][j][i-64]
    __shared__ float bsh[64];
    __shared__ float ssh[8][128];     // per-warp staged [msg | interact]

    int t = threadIdx.x, lane = t & 31, wid = t >> 5;

    const float* W1k = W1 + k * 4096;
    const float* W2k = W2 + k * 4096;
    for (int idx = t; idx < 128 * 64; idx += 256) {
        int i = idx >> 6, j = idx & 63;
        Wsh[idx] = (i < 64) ? W1k[j * 64 + i] : W2k[j * 64 + (i - 64)];
    }
    if (t < 64) bsh[t] = b1[k * 64 + t] + b2[k * 64 + t];
    __syncthreads();

    const int koff = k * 64;
    int r0 = blockIdx.x * rows_per_block;
    int r1 = min(r0 + rows_per_block, N_NODES);

    for (int r = r0 + wid; r < r1; r += 8) {
        // ---- SpMM: warp gathers this row's message (2 floats per lane) ----
        int start = d_rowptr[r];
        int len   = d_counts[r];
        float a0 = 0.f, a1 = 0.f;
        #pragma unroll 4
        for (int e = start; e < start + len; ++e) {
            int2 cv = d_perm[e];                         // uniform across warp
            float v = __int_as_float(cv.y);
            float2 xv = *(const float2*)(out + (size_t)cv.x * 256 + koff + 2 * lane);
            a0 += v * xv.x;
            a1 += v * xv.y;
        }
        float2 xr = *(const float2*)(out + (size_t)r * 256 + koff + 2 * lane);

        // ---- stage s = [msg | msg*x] into shared ----
        __syncwarp();
        float* s = ssh[wid];
        s[2 * lane]          = a0;
        s[2 * lane + 1]      = a1;
        s[64 + 2 * lane]     = a0 * xr.x;
        s[64 + 2 * lane + 1] = a1 * xr.y;
        __syncwarp();

        // ---- dense: lane computes outputs j = 2*lane, 2*lane+1 ----
        unsigned long long acc = pack2(bsh[2 * lane], bsh[2 * lane + 1]);
        const float2* Wp = (const float2*)Wsh + lane;   // row i at Wp[i*32]
        #pragma unroll
        for (int i = 0; i < 128; i += 4) {
            float4 s4 = *(const float4*)&s[i];          // broadcast LDS.128
            ffma2(acc, s4.x, Wp[(i + 0) * 32]);
            ffma2(acc, s4.y, Wp[(i + 1) * 32]);
            ffma2(acc, s4.z, Wp[(i + 2) * 32]);
            ffma2(acc, s4.w, Wp[(i + 3) * 32]);
        }
        float h0, h1;
        unpack2(acc, h0, h1);
        h0 = h0 > 0.f ? h0 : 0.2f * h0;                 // leaky_relu(0.2)
        h1 = h1 > 0.f ? h1 : 0.2f * h1;

        float sq = h0 * h0 + h1 * h1;
        #pragma unroll
        for (int m = 16; m; m >>= 1) sq += __shfl_xor_sync(0xffffffffu, sq, m);
        float nrm = sqrtf(sq);
        float inv = 1.0f / fmaxf(nrm, 1e-12f);

        *(float2*)(out + (size_t)r * 256 + koff + 64 + 2 * lane) =
            make_float2(h0 * inv, h1 * inv);
    }
}

// ---------------- launch ----------------
extern "C" void kernel_launch(void* const* d_in, const int* in_sizes, int n_in,
                              void* d_out, int out_size) {
    const float* ue   = (const float*)d_in[0];
    const float* ie   = (const float*)d_in[1];
    const float* W1   = (const float*)d_in[2];
    const float* b1   = (const float*)d_in[3];
    const float* W2   = (const float*)d_in[4];
    const float* b2   = (const float*)d_in[5];
    const float* vals = (const float*)d_in[6];
    const int*   rows = (const int*)d_in[7];
    const int*   cols = (const int*)d_in[8];
    float* out = (float*)d_out;
    int e = in_sizes[6];
    int L = in_sizes[2] / (64 * 64);

    // CSR build
    k_zero<<<(N_NODES + 255) / 256, 256>>>(N_NODES);
    k_hist<<<(e + 255) / 256, 256>>>(rows, e);
    k_scanA<<<N_SCAN_BLKS, SCAN_BLK>>>(N_NODES);
    k_scanB<<<1, 256>>>(N_SCAN_BLKS);
    k_scanC<<<N_SCAN_BLKS, SCAN_BLK>>>(N_NODES);
    k_scatter<<<(e + 255) / 256, 256>>>(rows, cols, vals, e);

    // layer 0 embeddings
    k_init<<<(N_NODES * 16 + 255) / 256, 256>>>(
        (const float4*)ue, (const float4*)ie, (float4*)out);

    // fused layers
    const int DG = 1184;                                   // 8 * 148 SMs
    const int rpb = (N_NODES + DG - 1) / DG;               // 127
    for (int k = 0; k < L; ++k)
        k_layer<<<DG, 256>>>(W1, b1, W2, b2, out, k, rpb);
}

// round 3
// speedup vs baseline: 1.0170x; 1.0169x over previous
#include <cuda_runtime.h>
#include <cuda_fp16.h>

#define N_USERS 100000
#define N_NODES 150000
#define E_MAX   4800000
#define SCAN_BLK 1024
#define N_SCAN_BLKS 147   // ceil(150000/1024)

// ---------------- static scratch (no allocation allowed) ----------------
__device__ int  d_counts[N_NODES];
__device__ int  d_rowptr[N_NODES];
__device__ int  d_cursor[N_NODES];
__device__ int  d_bsums[256];
__device__ int  d_boff[256];
__device__ int2 d_perm[E_MAX];                 // {col, val_bits} interleaved
__device__ __half2 d_x16[2][N_NODES * 32];     // ping-pong fp16 copy of current x slice

// ---------------- CSR build ----------------
__global__ void k_zero(int n) {
    int i = blockIdx.x * blockDim.x + threadIdx.x;
    if (i < n) d_counts[i] = 0;
}

__global__ void k_hist(const int* __restrict__ rows, int e) {
    int i = blockIdx.x * blockDim.x + threadIdx.x;
    if (i < e) atomicAdd(&d_counts[rows[i]], 1);
}

__global__ void k_scanA(int n) {
    __shared__ int sh[SCAN_BLK];
    int t = threadIdx.x;
    int idx = blockIdx.x * SCAN_BLK + t;
    int v = (idx < n) ? d_counts[idx] : 0;
    sh[t] = v;
    __syncthreads();
    for (int off = 1; off < SCAN_BLK; off <<= 1) {
        int x = (t >= off) ? sh[t - off] : 0;
        __syncthreads();
        sh[t] += x;
        __syncthreads();
    }
    if (idx < n) d_rowptr[idx] = sh[t] - v;     // exclusive within block
    if (t == SCAN_BLK - 1) d_bsums[blockIdx.x] = sh[t];
}

__global__ void k_scanB(int nb) {
    __shared__ int sh[256];
    int t = threadIdx.x;
    int v = (t < nb) ? d_bsums[t] : 0;
    sh[t] = v;
    __syncthreads();
    for (int off = 1; off < 256; off <<= 1) {
        int x = (t >= off) ? sh[t - off] : 0;
        __syncthreads();
        sh[t] += x;
        __syncthreads();
    }
    d_boff[t] = sh[t] - v;                       // exclusive block offsets
}

__global__ void k_scanC(int n) {
    int t = threadIdx.x;
    int idx = blockIdx.x * SCAN_BLK + t;
    if (idx < n) {
        int val = d_rowptr[idx] + d_boff[blockIdx.x];
        d_rowptr[idx] = val;
        d_cursor[idx] = val;
    }
}

__global__ void k_scatter(const int* __restrict__ rows,
                          const int* __restrict__ cols,
                          const float* __restrict__ vals, int e) {
    int i = blockIdx.x * blockDim.x + threadIdx.x;
    if (i < e) {
        int r = rows[i];
        int p = atomicAdd(&d_cursor[r], 1);
        d_perm[p] = make_int2(cols[i], __float_as_int(vals[i]));
    }
}

// ------- write layer-0 embeddings into out[:, 0:64] and fp16 buffer 0 -------
__global__ void k_init(const float4* __restrict__ ue,
                       const float4* __restrict__ ie,
                       float4* __restrict__ out) {
    int i = blockIdx.x * blockDim.x + threadIdx.x;   // over N_NODES*16
    if (i < N_NODES * 16) {
        int node = i >> 4, d4 = i & 15;
        float4 v = (node < N_USERS) ? ue[node * 16 + d4]
                                    : ie[(node - N_USERS) * 16 + d4];
        out[node * 64 + d4] = v;   // out row = 256 floats = 64 float4
        d_x16[0][node * 32 + 2 * d4]     = __floats2half2_rn(v.x, v.y);
        d_x16[0][node * 32 + 2 * d4 + 1] = __floats2half2_rn(v.z, v.w);
    }
}

// ---------------- packed fp32x2 helpers (Blackwell) ----------------
__device__ __forceinline__ unsigned long long pack2(float a, float b) {
    unsigned long long r;
    asm("mov.b64 %0,{%1,%2};" : "=l"(r) : "f"(a), "f"(b));
    return r;
}
__device__ __forceinline__ void unpack2(unsigned long long v, float& a, float& b) {
    asm("mov.b64 {%0,%1},%2;" : "=f"(a), "=f"(b) : "l"(v));
}
__device__ __forceinline__ void ffma2(unsigned long long& acc, float s, float2 w) {
    asm("{\n\t"
        ".reg .b64 sa, wb;\n\t"
        "mov.b64 sa,{%1,%1};\n\t"
        "mov.b64 wb,{%2,%3};\n\t"
        "fma.rn.f32x2 %0, sa, wb, %0;\n\t"
        "}"
        : "+l"(acc) : "f"(s), "f"(w.x), "f"(w.y));
}

// ---------------- fused layer: SpMM + dense + leaky + L2-norm ----------------
__global__ __launch_bounds__(256, 6) void k_layer(
    const float* __restrict__ W1, const float* __restrict__ b1,
    const float* __restrict__ W2, const float* __restrict__ b2,
    float* out, int k, int rows_per_block, int write16)
{
    __shared__ float Wsh[128 * 64];   // [i][j]: i<64 -> W1[k][j][i], i>=64 -> W2[k][j][i-64]
    __shared__ float bsh[64];
    __shared__ float ssh[8][128];     // per-warp staged [msg | interact]

    int t = threadIdx.x, lane = t & 31, wid = t >> 5;
    int src = k & 1, dst = src ^ 1;
    const __half2* __restrict__ xs = d_x16[src];

    const float* W1k = W1 + k * 4096;
    const float* W2k = W2 + k * 4096;
    for (int idx = t; idx < 128 * 64; idx += 256) {
        int i = idx >> 6, j = idx & 63;
        Wsh[idx] = (i < 64) ? W1k[j * 64 + i] : W2k[j * 64 + (i - 64)];
    }
    if (t < 64) bsh[t] = b1[k * 64 + t] + b2[k * 64 + t];
    __syncthreads();

    const int koff = k * 64;
    int r0 = blockIdx.x * rows_per_block;
    int r1 = min(r0 + rows_per_block, N_NODES);

    for (int r = r0 + wid; r < r1; r += 8) {
        // ---- SpMM: warp gathers this row's message (half2 per lane) ----
        int start = d_rowptr[r];
        int len   = d_counts[r];
        float a0 = 0.f, a1 = 0.f;
        #pragma unroll 4
        for (int e = start; e < start + len; ++e) {
            int2 cv = __ldcs(&d_perm[e]);                // uniform across warp, streaming
            float v = __int_as_float(cv.y);
            __half2 h = __ldcg(&xs[(size_t)cv.x * 32 + lane]);
            float2 xv = __half22float2(h);
            a0 += v * xv.x;
            a1 += v * xv.y;
        }
        float2 xr = *(const float2*)(out + (size_t)r * 256 + koff + 2 * lane);

        // ---- stage s = [msg | msg*x] into shared ----
        __syncwarp();
        float* s = ssh[wid];
        s[2 * lane]          = a0;
        s[2 * lane + 1]      = a1;
        s[64 + 2 * lane]     = a0 * xr.x;
        s[64 + 2 * lane + 1] = a1 * xr.y;
        __syncwarp();

        // ---- dense: lane computes outputs j = 2*lane, 2*lane+1 ----
        unsigned long long acc = pack2(bsh[2 * lane], bsh[2 * lane + 1]);
        const float2* Wp = (const float2*)Wsh + lane;   // row i at Wp[i*32]
        #pragma unroll
        for (int i = 0; i < 128; i += 4) {
            float4 s4 = *(const float4*)&s[i];          // broadcast LDS.128
            ffma2(acc, s4.x, Wp[(i + 0) * 32]);
            ffma2(acc, s4.y, Wp[(i + 1) * 32]);
            ffma2(acc, s4.z, Wp[(i + 2) * 32]);
            ffma2(acc, s4.w, Wp[(i + 3) * 32]);
        }
        float h0, h1;
        unpack2(acc, h0, h1);
        h0 = h0 > 0.f ? h0 : 0.2f * h0;                 // leaky_relu(0.2)
        h1 = h1 > 0.f ? h1 : 0.2f * h1;

        float sq = h0 * h0 + h1 * h1;
        #pragma unroll
        for (int m = 16; m; m >>= 1) sq += __shfl_xor_sync(0xffffffffu, sq, m);
        float nrm = sqrtf(sq);
        float inv = 1.0f / fmaxf(nrm, 1e-12f);
        float o0 = h0 * inv, o1 = h1 * inv;

        *(float2*)(out + (size_t)r * 256 + koff + 64 + 2 * lane) = make_float2(o0, o1);
        if (write16)
            d_x16[dst][(size_t)r * 32 + lane] = __floats2half2_rn(o0, o1);
    }
}

// ---------------- launch ----------------
extern "C" void kernel_launch(void* const* d_in, const int* in_sizes, int n_in,
                              void* d_out, int out_size) {
    const float* ue   = (const float*)d_in[0];
    const float* ie   = (const float*)d_in[1];
    const float* W1   = (const float*)d_in[2];
    const float* b1   = (const float*)d_in[3];
    const float* W2   = (const float*)d_in[4];
    const float* b2   = (const float*)d_in[5];
    const float* vals = (const float*)d_in[6];
    const int*   rows = (const int*)d_in[7];
    const int*   cols = (const int*)d_in[8];
    float* out = (float*)d_out;
    int e = in_sizes[6];
    int L = in_sizes[2] / (64 * 64);

    // CSR build
    k_zero<<<(N_NODES + 255) / 256, 256>>>(N_NODES);
    k_hist<<<(e + 255) / 256, 256>>>(rows, e);
    k_scanA<<<N_SCAN_BLKS, SCAN_BLK>>>(N_NODES);
    k_scanB<<<1, 256>>>(N_SCAN_BLKS);
    k_scanC<<<N_SCAN_BLKS, SCAN_BLK>>>(N_NODES);
    k_scatter<<<(e + 255) / 256, 256>>>(rows, cols, vals, e);

    // layer 0 embeddings (fp32 out + fp16 gather buffer)
    k_init<<<(N_NODES * 16 + 255) / 256, 256>>>(
        (const float4*)ue, (const float4*)ie, (float4*)out);

    // fused layers — 888 blocks = 6 resident/SM on 148 SMs = exactly one wave
    const int DG = 888;
    const int rpb = (N_NODES + DG - 1) / DG;             // 169
    for (int k = 0; k < L; ++k)
        k_layer<<<DG, 256>>>(W1, b1, W2, b2, out, k, rpb, (k + 1 < L) ? 1 : 0);
}